// round 14
// baseline (speedup 1.0000x reference)
#include <cuda_runtime.h>
#include <cuda_fp16.h>
#include <cstdint>
#include <math.h>

namespace {
constexpr int B_ = 64, C_ = 512, CR_ = 128, HW_ = 1024, KP_ = 256;
constexpr long OUT_ELEMS = (long)B_ * C_ * HW_;
}

// fp16 planes. hi+lo only on the softmax-feeding (A-side) operands.
__device__ __align__(256) unsigned short g_phih[B_*4*CR_*KP_];                       // B in att
__device__ __align__(256) unsigned short g_thh [B_*4*CR_*KP_], g_thl [B_*4*CR_*KP_]; // A in att
__device__ __align__(256) unsigned short g_gvh [B_*4*CR_*KP_];                       // B in out5
__device__ __align__(256) unsigned short g_atth[(long)B_*4*KP_*KP_];                 // A in out5
__device__ __align__(256) unsigned short g_midh[B_*4*KP_*CR_];                       // B in mask
__device__ __align__(256) unsigned short g_w3h[3*CR_*C_], g_w3l[3*CR_*C_];           // A in conv
__device__ __align__(256) unsigned short g_wmh[C_*CR_];                              // A in mask
__device__ __align__(256) float g_part[B_*4];
__device__ __align__(256) float g_y[B_*4];

// ------------------------------ helpers ------------------------------------
__device__ __forceinline__ uint32_t smem_u32(const void* p) {
    uint32_t a;
    asm("{ .reg .u64 t; cvta.to.shared.u64 t, %1; cvt.u32.u64 %0, t; }" : "=r"(a) : "l"(p));
    return a;
}
__device__ __forceinline__ void mma16816(float* d, uint32_t a0, uint32_t a1, uint32_t a2,
                                         uint32_t a3, uint32_t b0, uint32_t b1) {
    asm volatile(
        "mma.sync.aligned.m16n8k16.row.col.f32.f16.f16.f32 "
        "{%0,%1,%2,%3}, {%4,%5,%6,%7}, {%8,%9}, {%0,%1,%2,%3};"
        : "+f"(d[0]), "+f"(d[1]), "+f"(d[2]), "+f"(d[3])
        : "r"(a0), "r"(a1), "r"(a2), "r"(a3), "r"(b0), "r"(b1));
}
__device__ __forceinline__ void ldsm4(uint32_t* r, uint32_t a) {
    asm volatile("ldmatrix.sync.aligned.m8n8.x4.shared.b16 {%0,%1,%2,%3}, [%4];"
        : "=r"(r[0]), "=r"(r[1]), "=r"(r[2]), "=r"(r[3]) : "r"(a));
}
__device__ __forceinline__ void ldsm4t(uint32_t* r, uint32_t a) {
    asm volatile("ldmatrix.sync.aligned.m8n8.x4.trans.shared.b16 {%0,%1,%2,%3}, [%4];"
        : "=r"(r[0]), "=r"(r[1]), "=r"(r[2]), "=r"(r[3]) : "r"(a));
}
__device__ __forceinline__ uint32_t a_addr(uint32_t base, int lane, int S, int m0, int k0) {
    int mat = lane >> 3, lim = lane & 7;
    return base + (uint32_t)((m0 + lim + ((mat & 1) << 3)) * S + k0 + ((mat >> 1) << 3)) * 2;
}
__device__ __forceinline__ uint32_t b_addr(uint32_t base, int lane, int S, int n0, int k0) {
    int mat = lane >> 3, lim = lane & 7;
    return base + (uint32_t)((n0 + lim + ((mat >> 1) << 3)) * S + k0 + ((mat & 1) << 3)) * 2;
}
__device__ __forceinline__ uint32_t at_addr(uint32_t base, int lane, int S, int k0, int m0) {
    int mat = lane >> 3, lim = lane & 7;
    return base + (uint32_t)((k0 + lim + ((mat >> 1) << 3)) * S + m0 + ((mat & 1) << 3)) * 2;
}
__device__ __forceinline__ uint32_t bt_addr(uint32_t base, int lane, int S, int k0, int n0) {
    int mat = lane >> 3, lim = lane & 7;
    return base + (uint32_t)((k0 + lim + ((mat & 1) << 3)) * S + n0 + ((mat >> 1) << 3)) * 2;
}
__device__ __forceinline__ uint32_t h2(float a, float b) {
    __half2 v = __floats2half2_rn(a, b);
    return *(uint32_t*)&v;
}
__device__ __forceinline__ void hl2(float a, float b, uint32_t& h, uint32_t& l) {
    __half ha = __float2half_rn(a), hb = __float2half_rn(b);
    float ra = a - __half2float(ha), rb = b - __half2float(hb);
    __half la = __float2half_rn(ra), lb = __float2half_rn(rb);
    h = (uint32_t)*(unsigned short*)&ha | ((uint32_t)*(unsigned short*)&hb << 16);
    l = (uint32_t)*(unsigned short*)&la | ((uint32_t)*(unsigned short*)&lb << 16);
}
__device__ __forceinline__ void cpa16(uint32_t s, const void* g) {
    size_t ga;
    asm("cvta.to.global.u64 %0, %1;" : "=l"(ga) : "l"(g));
    asm volatile("cp.async.cg.shared.global [%0], [%1], 16;" :: "r"(s), "l"(ga) : "memory");
}
#define CPA_COMMIT() asm volatile("cp.async.commit_group;" ::: "memory")
#define CPA_WAIT0()  asm volatile("cp.async.wait_group 0;" ::: "memory")
#define CPA_WAIT2()  asm volatile("cp.async.wait_group 2;" ::: "memory")
__device__ __forceinline__ float hsum2(uint32_t v) {
    __half2 hv = *(__half2*)&v;
    float2 f = __half22float2(hv);
    return f.x + f.y;
}
__device__ __forceinline__ float hsum8(uint4 u) {
    return hsum2(u.x) + hsum2(u.y) + hsum2(u.z) + hsum2(u.w);
}

// ============ prep (3 launches so conv lands at profiler index 3) ==========
__global__ __launch_bounds__(256) void k_prep_w3(const float* __restrict__ wp,
    const float* __restrict__ wt, const float* __restrict__ wg)
{
    int i = blockIdx.x * 256 + threadIdx.x;      // 196608
    const float* s = (i < 65536) ? wp : (i < 131072) ? wt : wg;
    float v = s[i & 65535];
    __half h = __float2half_rn(v);
    float r = v - __half2float(h);
    __half l = __float2half_rn(r);
    g_w3h[i] = *(unsigned short*)&h; g_w3l[i] = *(unsigned short*)&l;
}
__global__ __launch_bounds__(256) void k_prep_wm(const float* __restrict__ wm)
{
    int i = blockIdx.x * 256 + threadIdx.x;      // 65536
    __half h = __float2half_rn(wm[i]);
    g_wmh[i] = *(unsigned short*)&h;
}
__global__ void k_zero_part()
{
    g_part[threadIdx.x] = 0.f;
}

// ========= K1: per-conv 1x1 conv blocks, 4-stage cp.async ring =============
// stage (ushorts): Wh [128][40] @0, Wl @5120, X [32][72] @10240; STG=12544
__global__ __launch_bounds__(256, 2) void k_conv3(
    const float* __restrict__ xa, const float* __restrict__ xb)
{
    extern __shared__ unsigned short sm[];
    const int STG = 12544;
    int tid = threadIdx.x, lane = tid & 31, wid = tid >> 5;
    int wm = wid >> 1, wn = wid & 1;
    int bx = blockIdx.x;
    int cv = bx % 3;                 // 0:phi(xa) 1:theta(xb) 2:g(xa+xb)
    int t = bx / 3;                  // 0..1023
    int b = t >> 4, tile = t & 15, hwb = tile * 64;
    const float* xa_b = xa + (long)b * C_ * HW_;
    const float* xb_b = xb + (long)b * C_ * HW_;
    uint32_t smb = smem_u32(sm);

    float acc[2][4][4];
#pragma unroll
    for (int i = 0; i < 2; i++)
#pragma unroll
        for (int j = 0; j < 4; j++)
#pragma unroll
            for (int q = 0; q < 4; q++) acc[i][j][q] = 0.f;

    int xc = tid >> 3, xp8 = (tid & 7) * 8;
    float4 ra0, ra1, rb0, rb1;

    auto issueW = [&](int c0, int st) {
#pragma unroll
        for (int j = 0; j < 5; j++) {
            int idx = tid + j * 256;          // 0..1279
            int pl = idx >= 640;
            int rem = pl ? idx - 640 : idx;   // 0..639
            int r = rem / 5, c8 = (rem % 5) * 8;
            long so = (long)cv * 65536 + (long)r * 512 + c0 + c8;
            uint32_t d0 = smb + (uint32_t)(st * STG + pl * 5120 + r * 40 + c8) * 2;
            cpa16(d0, pl ? &g_w3l[so] : &g_w3h[so]);
        }
    };
    auto loadX = [&](int c0) {
        long ga = (long)(c0 + xc) * HW_ + hwb + xp8;
        if (cv != 1) { ra0 = *(const float4*)&xa_b[ga]; ra1 = *(const float4*)&xa_b[ga + 4]; }
        if (cv != 0) { rb0 = *(const float4*)&xb_b[ga]; rb1 = *(const float4*)&xb_b[ga + 4]; }
    };
    auto storeX = [&](int st) {
        unsigned short* X = sm + st * STG + 10240;
        uint4 v;
        if (cv == 0)
            v = make_uint4(h2(ra0.x, ra0.y), h2(ra0.z, ra0.w), h2(ra1.x, ra1.y), h2(ra1.z, ra1.w));
        else if (cv == 1)
            v = make_uint4(h2(rb0.x, rb0.y), h2(rb0.z, rb0.w), h2(rb1.x, rb1.y), h2(rb1.z, rb1.w));
        else
            v = make_uint4(h2(ra0.x + rb0.x, ra0.y + rb0.y), h2(ra0.z + rb0.z, ra0.w + rb0.w),
                           h2(ra1.x + rb1.x, ra1.y + rb1.y), h2(ra1.z + rb1.z, ra1.w + rb1.w));
        *(uint4*)&X[xc * 72 + xp8] = v;
    };

    // prologue: W stages 0..2 in flight; X(0) staged
    issueW(0, 0);  CPA_COMMIT();
    issueW(32, 1); CPA_COMMIT();
    issueW(64, 2); CPA_COMMIT();
    loadX(0);
    CPA_WAIT2();          // W(0) complete (W1, W2 may still be in flight)
    storeX(0);
    __syncthreads();

    for (int ch = 0; ch < 16; ch++) {
        int st = ch & 3;
        if (ch < 13) issueW((ch + 3) * 32, (ch + 3) & 3);
        CPA_COMMIT();                    // empty group when ch>=13 keeps drain invariant
        if (ch < 15) loadX((ch + 1) * 32);

        uint32_t sstg = smb + (uint32_t)(st * STG) * 2;
        int m0 = wm * 32;
#pragma unroll
        for (int ks = 0; ks < 32; ks += 16) {
            uint32_t Wh = sstg, Wl = sstg + 5120 * 2, Xh = sstg + 10240 * 2;
            uint32_t ah[2][4], al[2][4];
#pragma unroll
            for (int mi = 0; mi < 2; mi++) {
                ldsm4(ah[mi], a_addr(Wh, lane, 40, m0 + mi * 16, ks));
                ldsm4(al[mi], a_addr(Wl, lane, 40, m0 + mi * 16, ks));
            }
#pragma unroll
            for (int np = 0; np < 2; np++) {
                uint32_t bh[4];
                ldsm4t(bh, bt_addr(Xh, lane, 72, ks, wn * 32 + np * 16));
#pragma unroll
                for (int s = 0; s < 2; s++) {
                    int ni = np * 2 + s;
#pragma unroll
                    for (int mi = 0; mi < 2; mi++) {
                        mma16816(acc[mi][ni], ah[mi][0], ah[mi][1], ah[mi][2], ah[mi][3], bh[2*s], bh[2*s+1]);
                        mma16816(acc[mi][ni], al[mi][0], al[mi][1], al[mi][2], al[mi][3], bh[2*s], bh[2*s+1]);
                    }
                }
            }
        }
        if (ch < 15) {
            storeX((ch + 1) & 3);
            CPA_WAIT2();                 // ensures W(ch+1) complete (2 newest may remain)
        }
        __syncthreads();
    }

    int g = lane >> 2, t2 = (lane & 3) * 2;
#pragma unroll
    for (int mi = 0; mi < 2; mi++)
#pragma unroll
        for (int ni = 0; ni < 4; ni++) {
            int m = wm * 32 + mi * 16 + g;
            int pix = hwb + wn * 32 + ni * 8 + t2;
            int h = pix >> 5, w = pix & 31;
            int p = ((h >> 4) << 1) + (w >> 4);
            int kk = ((h & 15) << 4) + (w & 15);
            long base = ((long)((b * 4 + p) * 128 + m)) * 256 + kk;
            if (cv == 1) {           // theta: hi + lo
                uint32_t hh, ll;
                hl2(acc[mi][ni][0], acc[mi][ni][1], hh, ll);
                *(uint32_t*)&g_thh[base] = hh; *(uint32_t*)&g_thl[base] = ll;
                hl2(acc[mi][ni][2], acc[mi][ni][3], hh, ll);
                *(uint32_t*)&g_thh[base + 8 * 256] = hh; *(uint32_t*)&g_thl[base + 8 * 256] = ll;
            } else {
                unsigned short* PH = (cv == 0) ? g_phih : g_gvh;
                *(uint32_t*)&PH[base] = h2(acc[mi][ni][0], acc[mi][ni][1]);
                *(uint32_t*)&PH[base + 8 * 256] = h2(acc[mi][ni][2], acc[mi][ni][3]);
            }
        }
}

// ============== means: y_pre[bp] = sum_c (sum_k th)(sum_l phi) ==============
__global__ __launch_bounds__(128) void k_means()
{
    __shared__ float red[128];
    int bp = blockIdx.x, c = threadIdx.x;
    long ro = ((long)bp * 128 + c) * 256;
    const uint4* th = (const uint4*)(g_thh + ro);
    const uint4* tl = (const uint4*)(g_thl + ro);
    const uint4* ph = (const uint4*)(g_phih + ro);
    float sth = 0.f, sph = 0.f;
#pragma unroll 4
    for (int j = 0; j < 32; j++) {
        sth += hsum8(th[j]) + hsum8(tl[j]);
        sph += hsum8(ph[j]);
    }
    red[c] = sth * sph;
    __syncthreads();
#pragma unroll
    for (int st = 64; st > 0; st >>= 1) {
        if (c < st) red[c] += red[c + st];
        __syncthreads();
    }
    if (c == 0) g_part[bp] = red[0];
}

// =============================== SE gate ===================================
__global__ void k_se(const float* __restrict__ se_w1, const float* __restrict__ se_w2,
                     float* __restrict__ y_out, int write_out)
{
    int b = threadIdx.x;
    if (b >= B_) return;
    float yp[4];
#pragma unroll
    for (int p = 0; p < 4; p++) yp[p] = g_part[b * 4 + p] * (1.f / 65536.f);
    float h0 = 0.f, h1 = 0.f;
#pragma unroll
    for (int p = 0; p < 4; p++) { h0 += yp[p] * se_w1[p]; h1 += yp[p] * se_w1[4 + p]; }
    h0 = fmaxf(h0, 0.f); h1 = fmaxf(h1, 0.f);
#pragma unroll
    for (int p = 0; p < 4; p++) {
        float z = h0 * se_w2[p * 2] + h1 * se_w2[p * 2 + 1];
        float yy = 1.f / (1.f + __expf(-z));
        g_y[b * 4 + p] = yy;
        if (write_out) y_out[b * 4 + p] = yy;
    }
}

// ====== K2: fused att (theta^T phi) + SE gate + patch softmax -> fp16 ======
// (stash version: N=64 tile, fp32 stash in smem)
__global__ __launch_bounds__(256, 1) void k_attsm()
{
    extern __shared__ unsigned short sm[];
    const int STG = 11008;
    float* stash = (float*)(sm + 2 * STG);  // [4][128][66]
    int tid = threadIdx.x, lane = tid & 31, wid = tid >> 5;
    int wm = wid >> 1, wn = wid & 1;
    int bxx = blockIdx.x, b = blockIdx.y;
    int kt = bxx >> 2, lt = bxx & 3;
    int k0g = kt * 128, l0g = lt * 64;
    uint32_t smb = smem_u32(sm);

    float acc[2][4][4];
#pragma unroll
    for (int i = 0; i < 2; i++)
#pragma unroll
        for (int j = 0; j < 4; j++)
#pragma unroll
            for (int q = 0; q < 4; q++) acc[i][j][q] = 0.f;

    auto issue = [&](int it, int st) {
        int p = it >> 2, c0 = (it & 3) * 32;
        long bp128 = (long)(b * 4 + p) * 128;
        uint32_t sb = smb + (uint32_t)(st * STG) * 2;
#pragma unroll
        for (int j = 0; j < 5; j++) {
            int idx = tid + j * 256;
            if (idx < 1024) {
                int pl = idx >> 9, rem = idx & 511;
                int cc = rem >> 4, k8 = (rem & 15) * 8;
                const unsigned short* src = (pl ? g_thl : g_thh) + (bp128 + c0 + cc) * 256 + k0g + k8;
                cpa16(sb + (uint32_t)(pl * 4352 + cc * 136 + k8) * 2, src);
            } else {
                int rem = idx - 1024;
                int cc = rem >> 3, l8 = (rem & 7) * 8;
                const unsigned short* src = g_phih + (bp128 + c0 + cc) * 256 + l0g + l8;
                cpa16(sb + (uint32_t)(8704 + cc * 72 + l8) * 2, src);
            }
        }
    };

    issue(0, 0); CPA_COMMIT(); CPA_WAIT0();
    __syncthreads();

    int g = lane >> 2, t2 = (lane & 3) * 2;
    for (int it = 0; it < 16; it++) {
        int buf = it & 1;
        if (it < 15) { issue(it + 1, buf ^ 1); CPA_COMMIT(); }
        uint32_t sstg = smb + (uint32_t)(buf * STG) * 2;
        int m0 = wm * 32;
#pragma unroll
        for (int ks = 0; ks < 32; ks += 16) {
            uint32_t ah[2][4], al[2][4];
#pragma unroll
            for (int mi = 0; mi < 2; mi++) {
                ldsm4t(ah[mi], at_addr(sstg,            lane, 136, ks, m0 + mi * 16));
                ldsm4t(al[mi], at_addr(sstg + 4352 * 2, lane, 136, ks, m0 + mi * 16));
            }
#pragma unroll
            for (int np = 0; np < 2; np++) {
                uint32_t bh[4];
                ldsm4t(bh, bt_addr(sstg + 8704 * 2, lane, 72, ks, wn * 32 + np * 16));
#pragma unroll
                for (int s = 0; s < 2; s++) {
                    int ni = np * 2 + s;
#pragma unroll
                    for (int mi = 0; mi < 2; mi++) {
                        mma16816(acc[mi][ni], ah[mi][0], ah[mi][1], ah[mi][2], ah[mi][3], bh[2*s], bh[2*s+1]);
                        mma16816(acc[mi][ni], al[mi][0], al[mi][1], al[mi][2], al[mi][3], bh[2*s], bh[2*s+1]);
                    }
                }
            }
        }
        if ((it & 3) == 3) {
            int p = it >> 2;
            float* sp = stash + p * 128 * 66;
#pragma unroll
            for (int mi = 0; mi < 2; mi++)
#pragma unroll
                for (int ni = 0; ni < 4; ni++) {
                    int m = wm * 32 + mi * 16 + g;
                    int l = wn * 32 + ni * 8 + t2;
                    sp[m * 66 + l]     = acc[mi][ni][0];
                    sp[m * 66 + l + 1] = acc[mi][ni][1];
                    sp[(m + 8) * 66 + l]     = acc[mi][ni][2];
                    sp[(m + 8) * 66 + l + 1] = acc[mi][ni][3];
                    acc[mi][ni][0] = acc[mi][ni][1] = acc[mi][ni][2] = acc[mi][ni][3] = 0.f;
                }
        }
        if (it < 15) CPA_WAIT0();
        __syncthreads();
    }

    float yv[4];
#pragma unroll
    for (int p = 0; p < 4; p++) yv[p] = g_y[b * 4 + p];
#pragma unroll
    for (int mi = 0; mi < 2; mi++)
#pragma unroll
        for (int ni = 0; ni < 4; ni++) {
            int m = wm * 32 + mi * 16 + g;
            int l = wn * 32 + ni * 8 + t2;
#pragma unroll
            for (int rr = 0; rr < 2; rr++) {
                int mm = m + rr * 8;
                float v0[4], v1[4];
#pragma unroll
                for (int p = 0; p < 4; p++) {
                    v0[p] = stash[p * 128 * 66 + mm * 66 + l] * yv[p];
                    v1[p] = stash[p * 128 * 66 + mm * 66 + l + 1] * yv[p];
                }
                float mx0 = fmaxf(fmaxf(v0[0], v0[1]), fmaxf(v0[2], v0[3]));
                float mx1 = fmaxf(fmaxf(v1[0], v1[1]), fmaxf(v1[2], v1[3]));
                float e0[4], e1[4], s0 = 0.f, s1 = 0.f;
#pragma unroll
                for (int p = 0; p < 4; p++) {
                    e0[p] = __expf(v0[p] - mx0); s0 += e0[p];
                    e1[p] = __expf(v1[p] - mx1); s1 += e1[p];
                }
                float i0 = 1.f / s0, i1 = 1.f / s1;
#pragma unroll
                for (int p = 0; p < 4; p++) {
                    long off = ((long)(b * 4 + p) * 256 + k0g + mm) * 256 + l0g + l;
                    *(uint32_t*)&g_atth[off] = h2(e0[p] * i0, e1[p] * i1);
                }
            }
        }
}

// ======== K5: mid[k][cr] = att @ g^T (1-pass) ==============================
__global__ __launch_bounds__(256) void k_out5()
{
    extern __shared__ unsigned short sm[];
    const int STG = 10240;
    int tid = threadIdx.x, lane = tid & 31, wid = tid >> 5;
    int wm = wid >> 1, wn = wid & 1;
    int bp = blockIdx.y;
    int k0 = blockIdx.x * 128;
    uint32_t smb = smem_u32(sm);

    float acc[2][8][4];
#pragma unroll
    for (int i = 0; i < 2; i++)
#pragma unroll
        for (int j = 0; j < 8; j++)
#pragma unroll
            for (int q = 0; q < 4; q++) acc[i][j][q] = 0.f;

    auto issue = [&](int ch, int st) {
        int l0 = ch * 32;
        uint32_t sb = smb + (uint32_t)(st * STG) * 2;
#pragma unroll
        for (int j = 0; j < 4; j++) {
            int idx = tid + j * 256;
            int pl = idx >> 9, rem = idx & 511;
            int r = rem >> 2, c8 = (rem & 3) * 8;
            const unsigned short* src;
            if (pl == 0) src = g_atth + ((long)bp * 256 + k0 + r) * 256 + l0 + c8;
            else         src = g_gvh  + ((long)bp * 128 + r) * 256 + l0 + c8;
            cpa16(sb + (uint32_t)(pl * 5120 + r * 40 + c8) * 2, src);
        }
    };

    issue(0, 0); CPA_COMMIT(); CPA_WAIT0();
    __syncthreads();

    for (int ch = 0; ch < 8; ch++) {
        int buf = ch & 1;
        if (ch < 7) { issue(ch + 1, buf ^ 1); CPA_COMMIT(); }
        uint32_t sstg = smb + (uint32_t)(buf * STG) * 2;
        int m0 = wm * 32;
#pragma unroll
        for (int ks = 0; ks < 32; ks += 16) {
            uint32_t ah[2][4];
#pragma unroll
            for (int mi = 0; mi < 2; mi++)
                ldsm4(ah[mi], a_addr(sstg, lane, 40, m0 + mi * 16, ks));
#pragma unroll
            for (int np = 0; np < 4; np++) {
                uint32_t bh[4];
                ldsm4(bh, b_addr(sstg + 5120 * 2, lane, 40, wn * 64 + np * 16, ks));
#pragma unroll
                for (int s = 0; s < 2; s++) {
                    int ni = np * 2 + s;
#pragma unroll
                    for (int mi = 0; mi < 2; mi++)
                        mma16816(acc[mi][ni], ah[mi][0], ah[mi][1], ah[mi][2], ah[mi][3], bh[2*s], bh[2*s+1]);
                }
            }
        }
        if (ch < 7) CPA_WAIT0();
        __syncthreads();
    }

    int g = lane >> 2, t2 = (lane & 3) * 2;
#pragma unroll
    for (int mi = 0; mi < 2; mi++)
#pragma unroll
        for (int ni = 0; ni < 8; ni++) {
            int m = k0 + wm * 32 + mi * 16 + g;
            int n = wn * 64 + ni * 8 + t2;
            long off = ((long)bp * 256 + m) * 128 + n;
            *(uint32_t*)&g_midh[off] = h2(acc[mi][ni][0], acc[mi][ni][1]);
            *(uint32_t*)&g_midh[off + 8 * 128] = h2(acc[mi][ni][2], acc[mi][ni][3]);
        }
}

// ======= K6: mask conv + residual (1-pass) =================================
__global__ __launch_bounds__(256) void k_mask(
    const float* __restrict__ xa, const float* __restrict__ xb, float* __restrict__ out)
{
    extern __shared__ unsigned short sm[];
    const int STG = 10240;
    int tid = threadIdx.x, lane = tid & 31, wid = tid >> 5;
    int wm = wid >> 1, wn = wid & 1;
    int bx = blockIdx.x;
    int b = bx >> 5, r5 = bx & 31;
    int p = r5 >> 3, mt = (r5 >> 1) & 3, nt = r5 & 1;
    int co0 = mt * 128, kk0 = nt * 128;
    int bp = b * 4 + p;
    int phh = (p >> 1) * 16, pww = (p & 1) * 16;
    uint32_t smb = smem_u32(sm);

    float acc[2][8][4];
#pragma unroll
    for (int i = 0; i < 2; i++)
#pragma unroll
        for (int j = 0; j < 8; j++)
#pragma unroll
            for (int q = 0; q < 4; q++) acc[i][j][q] = 0.f;

    auto issue = [&](int ch, int st) {
        int c0 = ch * 32;
        uint32_t sb = smb + (uint32_t)(st * STG) * 2;
#pragma unroll
        for (int j = 0; j < 4; j++) {
            int idx = tid + j * 256;
            int pl = idx >> 9, rem = idx & 511;
            int r = rem >> 2, c8 = (rem & 3) * 8;
            const unsigned short* src;
            if (pl == 0) src = g_wmh + (long)(co0 + r) * 128 + c0 + c8;
            else         src = g_midh + ((long)bp * 256 + kk0 + r) * 128 + c0 + c8;
            cpa16(sb + (uint32_t)(pl * 5120 + r * 40 + c8) * 2, src);
        }
    };

    issue(0, 0); CPA_COMMIT(); CPA_WAIT0();
    __syncthreads();

    for (int ch = 0; ch < 4; ch++) {
        int buf = ch & 1;
        if (ch < 3) { issue(ch + 1, buf ^ 1); CPA_COMMIT(); }
        uint32_t sstg = smb + (uint32_t)(buf * STG) * 2;
        int m0 = wm * 32;
#pragma unroll
        for (int ks = 0; ks < 32; ks += 16) {
            uint32_t ah[2][4];
#pragma unroll
            for (int mi = 0; mi < 2; mi++)
                ldsm4(ah[mi], a_addr(sstg, lane, 40, m0 + mi * 16, ks));
#pragma unroll
            for (int np = 0; np < 4; np++) {
                uint32_t bh[4];
                ldsm4(bh, b_addr(sstg + 5120 * 2, lane, 40, wn * 64 + np * 16, ks));
#pragma unroll
                for (int s = 0; s < 2; s++) {
                    int ni = np * 2 + s;
#pragma unroll
                    for (int mi = 0; mi < 2; mi++)
                        mma16816(acc[mi][ni], ah[mi][0], ah[mi][1], ah[mi][2], ah[mi][3], bh[2*s], bh[2*s+1]);
                }
            }
        }
        if (ch < 3) CPA_WAIT0();
        __syncthreads();
    }

    int g = lane >> 2, t2 = (lane & 3) * 2;
#pragma unroll
    for (int mi = 0; mi < 2; mi++)
#pragma unroll
        for (int ni = 0; ni < 8; ni++) {
            int m = co0 + wm * 32 + mi * 16 + g;
            int kk = kk0 + wn * 64 + ni * 8 + t2;
            int h = phh + (kk >> 4), w = pww + (kk & 15);
            long oa = ((long)b * C_ + m) * HW_ + h * 32 + w;
            float2 va = *(const float2*)&xa[oa];
            float2 vb = *(const float2*)&xb[oa];
            *(float2*)&out[oa] = make_float2(acc[mi][ni][0] + va.x + vb.x,
                                             acc[mi][ni][1] + va.y + vb.y);
            long ob = oa + (long)8 * HW_;
            float2 va2 = *(const float2*)&xa[ob];
            float2 vb2 = *(const float2*)&xb[ob];
            *(float2*)&out[ob] = make_float2(acc[mi][ni][2] + va2.x + vb2.x,
                                             acc[mi][ni][3] + va2.y + vb2.y);
        }
}

// ---------------------------------------------------------------------------
extern "C" void kernel_launch(void* const* d_in, const int* in_sizes, int n_in,
                              void* d_out, int out_size)
{
    const float* xa      = (const float*)d_in[0];
    const float* xb      = (const float*)d_in[1];
    const float* w_phi   = (const float*)d_in[2];
    const float* w_theta = (const float*)d_in[3];
    const float* w_g     = (const float*)d_in[4];
    const float* w_mask  = (const float*)d_in[5];
    const float* se_w1   = (const float*)d_in[6];
    const float* se_w2   = (const float*)d_in[7];
    float* out = (float*)d_out;

    const int SM_CONV = 4 * 12544 * 2;                     // 100352 (4 stages)
    const int SM_ATT  = 2 * 11008 * 2 + 4 * 128 * 66 * 4;  // 179200
    const int SM_GEMM = 2 * 10240 * 2;                     // 40960
    cudaFuncSetAttribute(k_conv3, cudaFuncAttributeMaxDynamicSharedMemorySize, SM_CONV);
    cudaFuncSetAttribute(k_attsm, cudaFuncAttributeMaxDynamicSharedMemorySize, SM_ATT);

    k_prep_w3<<<768, 256>>>(w_phi, w_theta, w_g);   // 0
    k_prep_wm<<<256, 256>>>(w_mask);                // 1
    k_zero_part<<<1, 256>>>();                      // 2
    k_conv3<<<3072, 256, SM_CONV>>>(xa, xb);        // 3  <- profiled
    k_means<<<256, 128>>>();                        // 4
    int write_y = ((long)out_size >= OUT_ELEMS + (long)B_ * 4) ? 1 : 0;
    k_se<<<1, 64>>>(se_w1, se_w2, out + OUT_ELEMS, write_y);  // 5
    k_attsm<<<dim3(8, 64), 256, SM_ATT>>>();        // 6
    k_out5<<<dim3(2, 256), 256, SM_GEMM>>>();       // 7
    k_mask<<<2048, 256, SM_GEMM>>>(xa, xb, out);    // 8
}

// round 15
// speedup vs baseline: 1.0431x; 1.0431x over previous
#include <cuda_runtime.h>
#include <cuda_fp16.h>
#include <cstdint>
#include <math.h>

namespace {
constexpr int B_ = 64, C_ = 512, CR_ = 128, HW_ = 1024, KP_ = 256;
constexpr long OUT_ELEMS = (long)B_ * C_ * HW_;
}

// fp16 planes. hi+lo only on the softmax-feeding (A-side) operands.
__device__ __align__(256) unsigned short g_phih[B_*4*CR_*KP_];                       // B in att
__device__ __align__(256) unsigned short g_thh [B_*4*CR_*KP_], g_thl [B_*4*CR_*KP_]; // A in att
__device__ __align__(256) unsigned short g_gvh [B_*4*CR_*KP_];                       // B in out5
__device__ __align__(256) unsigned short g_atth[(long)B_*4*KP_*KP_];                 // A in out5
__device__ __align__(256) unsigned short g_midh[B_*4*KP_*CR_];                       // B in mask
__device__ __align__(256) unsigned short g_w3h[3*CR_*C_], g_w3l[3*CR_*C_];           // A in conv
__device__ __align__(256) unsigned short g_wmh[C_*CR_];                              // A in mask
__device__ __align__(256) float g_part[B_*4];
__device__ __align__(256) float g_y[B_*4];

// ------------------------------ helpers ------------------------------------
__device__ __forceinline__ uint32_t smem_u32(const void* p) {
    uint32_t a;
    asm("{ .reg .u64 t; cvta.to.shared.u64 t, %1; cvt.u32.u64 %0, t; }" : "=r"(a) : "l"(p));
    return a;
}
__device__ __forceinline__ void mma16816(float* d, uint32_t a0, uint32_t a1, uint32_t a2,
                                         uint32_t a3, uint32_t b0, uint32_t b1) {
    asm volatile(
        "mma.sync.aligned.m16n8k16.row.col.f32.f16.f16.f32 "
        "{%0,%1,%2,%3}, {%4,%5,%6,%7}, {%8,%9}, {%0,%1,%2,%3};"
        : "+f"(d[0]), "+f"(d[1]), "+f"(d[2]), "+f"(d[3])
        : "r"(a0), "r"(a1), "r"(a2), "r"(a3), "r"(b0), "r"(b1));
}
__device__ __forceinline__ void ldsm4(uint32_t* r, uint32_t a) {
    asm volatile("ldmatrix.sync.aligned.m8n8.x4.shared.b16 {%0,%1,%2,%3}, [%4];"
        : "=r"(r[0]), "=r"(r[1]), "=r"(r[2]), "=r"(r[3]) : "r"(a));
}
__device__ __forceinline__ void ldsm4t(uint32_t* r, uint32_t a) {
    asm volatile("ldmatrix.sync.aligned.m8n8.x4.trans.shared.b16 {%0,%1,%2,%3}, [%4];"
        : "=r"(r[0]), "=r"(r[1]), "=r"(r[2]), "=r"(r[3]) : "r"(a));
}
__device__ __forceinline__ uint32_t a_addr(uint32_t base, int lane, int S, int m0, int k0) {
    int mat = lane >> 3, lim = lane & 7;
    return base + (uint32_t)((m0 + lim + ((mat & 1) << 3)) * S + k0 + ((mat >> 1) << 3)) * 2;
}
__device__ __forceinline__ uint32_t b_addr(uint32_t base, int lane, int S, int n0, int k0) {
    int mat = lane >> 3, lim = lane & 7;
    return base + (uint32_t)((n0 + lim + ((mat >> 1) << 3)) * S + k0 + ((mat & 1) << 3)) * 2;
}
__device__ __forceinline__ uint32_t at_addr(uint32_t base, int lane, int S, int k0, int m0) {
    int mat = lane >> 3, lim = lane & 7;
    return base + (uint32_t)((k0 + lim + ((mat >> 1) << 3)) * S + m0 + ((mat & 1) << 3)) * 2;
}
__device__ __forceinline__ uint32_t bt_addr(uint32_t base, int lane, int S, int k0, int n0) {
    int mat = lane >> 3, lim = lane & 7;
    return base + (uint32_t)((k0 + lim + ((mat & 1) << 3)) * S + n0 + ((mat >> 1) << 3)) * 2;
}
__device__ __forceinline__ uint32_t h2(float a, float b) {
    __half2 v = __floats2half2_rn(a, b);
    return *(uint32_t*)&v;
}
__device__ __forceinline__ void hl2(float a, float b, uint32_t& h, uint32_t& l) {
    __half ha = __float2half_rn(a), hb = __float2half_rn(b);
    float ra = a - __half2float(ha), rb = b - __half2float(hb);
    __half la = __float2half_rn(ra), lb = __float2half_rn(rb);
    h = (uint32_t)*(unsigned short*)&ha | ((uint32_t)*(unsigned short*)&hb << 16);
    l = (uint32_t)*(unsigned short*)&la | ((uint32_t)*(unsigned short*)&lb << 16);
}
__device__ __forceinline__ void cpa16(uint32_t s, const void* g) {
    size_t ga;
    asm("cvta.to.global.u64 %0, %1;" : "=l"(ga) : "l"(g));
    asm volatile("cp.async.cg.shared.global [%0], [%1], 16;" :: "r"(s), "l"(ga) : "memory");
}
#define CPA_COMMIT() asm volatile("cp.async.commit_group;" ::: "memory")
#define CPA_WAIT0()  asm volatile("cp.async.wait_group 0;" ::: "memory")
__device__ __forceinline__ float hsum2(uint32_t v) {
    __half2 hv = *(__half2*)&v;
    float2 f = __half22float2(hv);
    return f.x + f.y;
}
__device__ __forceinline__ float hsum8(uint4 u) {
    return hsum2(u.x) + hsum2(u.y) + hsum2(u.z) + hsum2(u.w);
}

// ============ prep (3 launches so conv lands at profiler index 3) ==========
__global__ __launch_bounds__(256) void k_prep_w3(const float* __restrict__ wp,
    const float* __restrict__ wt, const float* __restrict__ wg)
{
    int i = blockIdx.x * 256 + threadIdx.x;      // 196608
    const float* s = (i < 65536) ? wp : (i < 131072) ? wt : wg;
    float v = s[i & 65535];
    __half h = __float2half_rn(v);
    float r = v - __half2float(h);
    __half l = __float2half_rn(r);
    g_w3h[i] = *(unsigned short*)&h; g_w3l[i] = *(unsigned short*)&l;
}
__global__ __launch_bounds__(256) void k_prep_wm(const float* __restrict__ wm)
{
    int i = blockIdx.x * 256 + threadIdx.x;      // 65536
    __half h = __float2half_rn(wm[i]);
    g_wmh[i] = *(unsigned short*)&h;
}
__global__ void k_zero_part()
{
    g_part[threadIdx.x] = 0.f;
}

// ===== K1: fused 3x 1x1 conv, 512 threads (16 warps, 4m x 4n), 2 stages ====
// stage (ushorts): W planes (cv,pl): (cv*2+pl)*5120 [128][40]; X t: 30720+t*2304 [32][72]
__global__ __launch_bounds__(512, 1) void k_conv3(
    const float* __restrict__ xa, const float* __restrict__ xb)
{
    extern __shared__ unsigned short sm[];
    const int STG = 37632;
    int tid = threadIdx.x, lane = tid & 31, wid = tid >> 5;
    int wm = wid >> 2, wn = wid & 3;     // 4 m-warps x 4 n-warps
    int bx = blockIdx.x;
    int b = bx >> 4, tile = bx & 15, hwb = tile * 64;
    const float* xa_b = xa + (long)b * C_ * HW_;
    const float* xb_b = xb + (long)b * C_ * HW_;
    uint32_t smb = smem_u32(sm);

    float acc[3][2][2][4];               // [cv][mi][s][4]
#pragma unroll
    for (int c = 0; c < 3; c++)
#pragma unroll
        for (int i = 0; i < 2; i++)
#pragma unroll
            for (int j = 0; j < 2; j++)
#pragma unroll
                for (int q = 0; q < 4; q++) acc[c][i][j][q] = 0.f;

    int xc = tid >> 4, xp4 = (tid & 15) * 4;   // 32 rows x 16 float4-quarters
    float4 ra, rb;

    auto issueW = [&](int c0, int st) {
#pragma unroll
        for (int j = 0; j < 3; j++) {
            int idx = tid + j * 512;           // 0..1535
            int wh = idx >> 9, rem = idx & 511;
            int r = rem >> 2, c8 = (rem & 3) * 8;
            long so = (long)wh * 65536 + (long)r * 512 + c0 + c8;
            uint32_t d0 = smb + (uint32_t)(st * STG + (wh * 2 + 0) * 5120 + r * 40 + c8) * 2;
            cpa16(d0, &g_w3h[so]);
            cpa16(d0 + 5120 * 2, &g_w3l[so]);
        }
    };
    auto loadX = [&](int c0) {
        long ga = (long)(c0 + xc) * HW_ + hwb + xp4;
        ra = *(const float4*)&xa_b[ga];
        rb = *(const float4*)&xb_b[ga];
    };
    auto storeX = [&](int st) {
        unsigned short* X = sm + st * STG + 30720;
        *(uint2*)&X[0 * 2304 + xc * 72 + xp4] = make_uint2(h2(ra.x, ra.y), h2(ra.z, ra.w));
        *(uint2*)&X[1 * 2304 + xc * 72 + xp4] = make_uint2(h2(rb.x, rb.y), h2(rb.z, rb.w));
        *(uint2*)&X[2 * 2304 + xc * 72 + xp4] = make_uint2(
            h2(ra.x + rb.x, ra.y + rb.y), h2(ra.z + rb.z, ra.w + rb.w));
    };

    issueW(0, 0); CPA_COMMIT();
    loadX(0);
    CPA_WAIT0();
    storeX(0);
    __syncthreads();

    for (int ch = 0; ch < 16; ch++) {
        int buf = ch & 1;
        if (ch < 15) {
            issueW((ch + 1) * 32, buf ^ 1); CPA_COMMIT();
            loadX((ch + 1) * 32);
        }
        uint32_t sstg = smb + (uint32_t)(buf * STG) * 2;
        int m0 = wm * 32, n0 = wn * 16;
#pragma unroll
        for (int ks = 0; ks < 32; ks += 16) {
#pragma unroll
            for (int cv = 0; cv < 3; cv++) {
                uint32_t Wh = sstg + (uint32_t)(cv * 2) * 5120 * 2;
                uint32_t Wl = Wh + 5120 * 2;
                uint32_t Xh = sstg + (uint32_t)(30720 + cv * 2304) * 2;
                uint32_t ah[2][4], al[2][4];
#pragma unroll
                for (int mi = 0; mi < 2; mi++) {
                    ldsm4(ah[mi], a_addr(Wh, lane, 40, m0 + mi * 16, ks));
                    ldsm4(al[mi], a_addr(Wl, lane, 40, m0 + mi * 16, ks));
                }
                uint32_t bh[4];
                ldsm4t(bh, bt_addr(Xh, lane, 72, ks, n0));
#pragma unroll
                for (int s = 0; s < 2; s++) {
#pragma unroll
                    for (int mi = 0; mi < 2; mi++) {
                        mma16816(acc[cv][mi][s], ah[mi][0], ah[mi][1], ah[mi][2], ah[mi][3], bh[2*s], bh[2*s+1]);
                        mma16816(acc[cv][mi][s], al[mi][0], al[mi][1], al[mi][2], al[mi][3], bh[2*s], bh[2*s+1]);
                    }
                }
            }
        }
        if (ch < 15) {
            storeX(buf ^ 1);
            CPA_WAIT0();
        }
        __syncthreads();
    }

    int g = lane >> 2, t2 = (lane & 3) * 2;
#pragma unroll
    for (int cv = 0; cv < 3; cv++) {
#pragma unroll
        for (int mi = 0; mi < 2; mi++)
#pragma unroll
            for (int s = 0; s < 2; s++) {
                int m = wm * 32 + mi * 16 + g;
                int pix = hwb + wn * 16 + s * 8 + t2;
                int h = pix >> 5, w = pix & 31;
                int p = ((h >> 4) << 1) + (w >> 4);
                int kk = ((h & 15) << 4) + (w & 15);
                long base = ((long)((b * 4 + p) * 128 + m)) * 256 + kk;
                if (cv == 1) {      // theta: hi + lo (A-side in att)
                    uint32_t hh, ll;
                    hl2(acc[cv][mi][s][0], acc[cv][mi][s][1], hh, ll);
                    *(uint32_t*)&g_thh[base] = hh; *(uint32_t*)&g_thl[base] = ll;
                    hl2(acc[cv][mi][s][2], acc[cv][mi][s][3], hh, ll);
                    *(uint32_t*)&g_thh[base + 8 * 256] = hh; *(uint32_t*)&g_thl[base + 8 * 256] = ll;
                } else {            // phi / g: hi only (B-side)
                    unsigned short* PH = (cv == 0) ? g_phih : g_gvh;
                    *(uint32_t*)&PH[base] = h2(acc[cv][mi][s][0], acc[cv][mi][s][1]);
                    *(uint32_t*)&PH[base + 8 * 256] = h2(acc[cv][mi][s][2], acc[cv][mi][s][3]);
                }
            }
    }
}

// ============== means: y_pre[bp] = sum_c (sum_k th)(sum_l phi) ==============
__global__ __launch_bounds__(128) void k_means()
{
    __shared__ float red[128];
    int bp = blockIdx.x, c = threadIdx.x;
    long ro = ((long)bp * 128 + c) * 256;
    const uint4* th = (const uint4*)(g_thh + ro);
    const uint4* tl = (const uint4*)(g_thl + ro);
    const uint4* ph = (const uint4*)(g_phih + ro);
    float sth = 0.f, sph = 0.f;
#pragma unroll 4
    for (int j = 0; j < 32; j++) {
        sth += hsum8(th[j]) + hsum8(tl[j]);
        sph += hsum8(ph[j]);
    }
    red[c] = sth * sph;
    __syncthreads();
#pragma unroll
    for (int st = 64; st > 0; st >>= 1) {
        if (c < st) red[c] += red[c + st];
        __syncthreads();
    }
    if (c == 0) g_part[bp] = red[0];
}

// =============================== SE gate ===================================
__global__ void k_se(const float* __restrict__ se_w1, const float* __restrict__ se_w2,
                     float* __restrict__ y_out, int write_out)
{
    int b = threadIdx.x;
    if (b >= B_) return;
    float yp[4];
#pragma unroll
    for (int p = 0; p < 4; p++) yp[p] = g_part[b * 4 + p] * (1.f / 65536.f);
    float h0 = 0.f, h1 = 0.f;
#pragma unroll
    for (int p = 0; p < 4; p++) { h0 += yp[p] * se_w1[p]; h1 += yp[p] * se_w1[4 + p]; }
    h0 = fmaxf(h0, 0.f); h1 = fmaxf(h1, 0.f);
#pragma unroll
    for (int p = 0; p < 4; p++) {
        float z = h0 * se_w2[p * 2] + h1 * se_w2[p * 2 + 1];
        float yy = 1.f / (1.f + __expf(-z));
        g_y[b * 4 + p] = yy;
        if (write_out) y_out[b * 4 + p] = yy;
    }
}

// ====== K2: fused att (theta^T phi) + SE gate + patch softmax -> fp16 ======
__global__ __launch_bounds__(256, 1) void k_attsm()
{
    extern __shared__ unsigned short sm[];
    const int STG = 11008;
    float* stash = (float*)(sm + 2 * STG);  // [4][128][66]
    int tid = threadIdx.x, lane = tid & 31, wid = tid >> 5;
    int wm = wid >> 1, wn = wid & 1;
    int bxx = blockIdx.x, b = blockIdx.y;
    int kt = bxx >> 2, lt = bxx & 3;
    int k0g = kt * 128, l0g = lt * 64;
    uint32_t smb = smem_u32(sm);

    float acc[2][4][4];
#pragma unroll
    for (int i = 0; i < 2; i++)
#pragma unroll
        for (int j = 0; j < 4; j++)
#pragma unroll
            for (int q = 0; q < 4; q++) acc[i][j][q] = 0.f;

    auto issue = [&](int it, int st) {
        int p = it >> 2, c0 = (it & 3) * 32;
        long bp128 = (long)(b * 4 + p) * 128;
        uint32_t sb = smb + (uint32_t)(st * STG) * 2;
#pragma unroll
        for (int j = 0; j < 5; j++) {
            int idx = tid + j * 256;
            if (idx < 1024) {
                int pl = idx >> 9, rem = idx & 511;
                int cc = rem >> 4, k8 = (rem & 15) * 8;
                const unsigned short* src = (pl ? g_thl : g_thh) + (bp128 + c0 + cc) * 256 + k0g + k8;
                cpa16(sb + (uint32_t)(pl * 4352 + cc * 136 + k8) * 2, src);
            } else {
                int rem = idx - 1024;
                int cc = rem >> 3, l8 = (rem & 7) * 8;
                const unsigned short* src = g_phih + (bp128 + c0 + cc) * 256 + l0g + l8;
                cpa16(sb + (uint32_t)(8704 + cc * 72 + l8) * 2, src);
            }
        }
    };

    issue(0, 0); CPA_COMMIT(); CPA_WAIT0();
    __syncthreads();

    int g = lane >> 2, t2 = (lane & 3) * 2;
    for (int it = 0; it < 16; it++) {
        int buf = it & 1;
        if (it < 15) { issue(it + 1, buf ^ 1); CPA_COMMIT(); }
        uint32_t sstg = smb + (uint32_t)(buf * STG) * 2;
        int m0 = wm * 32;
#pragma unroll
        for (int ks = 0; ks < 32; ks += 16) {
            uint32_t ah[2][4], al[2][4];
#pragma unroll
            for (int mi = 0; mi < 2; mi++) {
                ldsm4t(ah[mi], at_addr(sstg,            lane, 136, ks, m0 + mi * 16));
                ldsm4t(al[mi], at_addr(sstg + 4352 * 2, lane, 136, ks, m0 + mi * 16));
            }
#pragma unroll
            for (int np = 0; np < 2; np++) {
                uint32_t bh[4];
                ldsm4t(bh, bt_addr(sstg + 8704 * 2, lane, 72, ks, wn * 32 + np * 16));
#pragma unroll
                for (int s = 0; s < 2; s++) {
                    int ni = np * 2 + s;
#pragma unroll
                    for (int mi = 0; mi < 2; mi++) {
                        mma16816(acc[mi][ni], ah[mi][0], ah[mi][1], ah[mi][2], ah[mi][3], bh[2*s], bh[2*s+1]);
                        mma16816(acc[mi][ni], al[mi][0], al[mi][1], al[mi][2], al[mi][3], bh[2*s], bh[2*s+1]);
                    }
                }
            }
        }
        if ((it & 3) == 3) {
            int p = it >> 2;
            float* sp = stash + p * 128 * 66;
#pragma unroll
            for (int mi = 0; mi < 2; mi++)
#pragma unroll
                for (int ni = 0; ni < 4; ni++) {
                    int m = wm * 32 + mi * 16 + g;
                    int l = wn * 32 + ni * 8 + t2;
                    sp[m * 66 + l]     = acc[mi][ni][0];
                    sp[m * 66 + l + 1] = acc[mi][ni][1];
                    sp[(m + 8) * 66 + l]     = acc[mi][ni][2];
                    sp[(m + 8) * 66 + l + 1] = acc[mi][ni][3];
                    acc[mi][ni][0] = acc[mi][ni][1] = acc[mi][ni][2] = acc[mi][ni][3] = 0.f;
                }
        }
        if (it < 15) CPA_WAIT0();
        __syncthreads();
    }

    float yv[4];
#pragma unroll
    for (int p = 0; p < 4; p++) yv[p] = g_y[b * 4 + p];
#pragma unroll
    for (int mi = 0; mi < 2; mi++)
#pragma unroll
        for (int ni = 0; ni < 4; ni++) {
            int m = wm * 32 + mi * 16 + g;
            int l = wn * 32 + ni * 8 + t2;
#pragma unroll
            for (int rr = 0; rr < 2; rr++) {
                int mm = m + rr * 8;
                float v0[4], v1[4];
#pragma unroll
                for (int p = 0; p < 4; p++) {
                    v0[p] = stash[p * 128 * 66 + mm * 66 + l] * yv[p];
                    v1[p] = stash[p * 128 * 66 + mm * 66 + l + 1] * yv[p];
                }
                float mx0 = fmaxf(fmaxf(v0[0], v0[1]), fmaxf(v0[2], v0[3]));
                float mx1 = fmaxf(fmaxf(v1[0], v1[1]), fmaxf(v1[2], v1[3]));
                float e0[4], e1[4], s0 = 0.f, s1 = 0.f;
#pragma unroll
                for (int p = 0; p < 4; p++) {
                    e0[p] = __expf(v0[p] - mx0); s0 += e0[p];
                    e1[p] = __expf(v1[p] - mx1); s1 += e1[p];
                }
                float i0 = 1.f / s0, i1 = 1.f / s1;
#pragma unroll
                for (int p = 0; p < 4; p++) {
                    long off = ((long)(b * 4 + p) * 256 + k0g + mm) * 256 + l0g + l;
                    *(uint32_t*)&g_atth[off] = h2(e0[p] * i0, e1[p] * i1);
                }
            }
        }
}

// ======== K5: mid[k][cr] = att @ g^T (1-pass) ==============================
__global__ __launch_bounds__(256) void k_out5()
{
    extern __shared__ unsigned short sm[];
    const int STG = 10240;
    int tid = threadIdx.x, lane = tid & 31, wid = tid >> 5;
    int wm = wid >> 1, wn = wid & 1;
    int bp = blockIdx.y;
    int k0 = blockIdx.x * 128;
    uint32_t smb = smem_u32(sm);

    float acc[2][8][4];
#pragma unroll
    for (int i = 0; i < 2; i++)
#pragma unroll
        for (int j = 0; j < 8; j++)
#pragma unroll
            for (int q = 0; q < 4; q++) acc[i][j][q] = 0.f;

    auto issue = [&](int ch, int st) {
        int l0 = ch * 32;
        uint32_t sb = smb + (uint32_t)(st * STG) * 2;
#pragma unroll
        for (int j = 0; j < 4; j++) {
            int idx = tid + j * 256;
            int pl = idx >> 9, rem = idx & 511;
            int r = rem >> 2, c8 = (rem & 3) * 8;
            const unsigned short* src;
            if (pl == 0) src = g_atth + ((long)bp * 256 + k0 + r) * 256 + l0 + c8;
            else         src = g_gvh  + ((long)bp * 128 + r) * 256 + l0 + c8;
            cpa16(sb + (uint32_t)(pl * 5120 + r * 40 + c8) * 2, src);
        }
    };

    issue(0, 0); CPA_COMMIT(); CPA_WAIT0();
    __syncthreads();

    for (int ch = 0; ch < 8; ch++) {
        int buf = ch & 1;
        if (ch < 7) { issue(ch + 1, buf ^ 1); CPA_COMMIT(); }
        uint32_t sstg = smb + (uint32_t)(buf * STG) * 2;
        int m0 = wm * 32;
#pragma unroll
        for (int ks = 0; ks < 32; ks += 16) {
            uint32_t ah[2][4];
#pragma unroll
            for (int mi = 0; mi < 2; mi++)
                ldsm4(ah[mi], a_addr(sstg, lane, 40, m0 + mi * 16, ks));
#pragma unroll
            for (int np = 0; np < 4; np++) {
                uint32_t bh[4];
                ldsm4(bh, b_addr(sstg + 5120 * 2, lane, 40, wn * 64 + np * 16, ks));
#pragma unroll
                for (int s = 0; s < 2; s++) {
                    int ni = np * 2 + s;
#pragma unroll
                    for (int mi = 0; mi < 2; mi++)
                        mma16816(acc[mi][ni], ah[mi][0], ah[mi][1], ah[mi][2], ah[mi][3], bh[2*s], bh[2*s+1]);
                }
            }
        }
        if (ch < 7) CPA_WAIT0();
        __syncthreads();
    }

    int g = lane >> 2, t2 = (lane & 3) * 2;
#pragma unroll
    for (int mi = 0; mi < 2; mi++)
#pragma unroll
        for (int ni = 0; ni < 8; ni++) {
            int m = k0 + wm * 32 + mi * 16 + g;
            int n = wn * 64 + ni * 8 + t2;
            long off = ((long)bp * 256 + m) * 128 + n;
            *(uint32_t*)&g_midh[off] = h2(acc[mi][ni][0], acc[mi][ni][1]);
            *(uint32_t*)&g_midh[off + 8 * 128] = h2(acc[mi][ni][2], acc[mi][ni][3]);
        }
}

// ======= K6: mask conv + residual (1-pass) =================================
__global__ __launch_bounds__(256) void k_mask(
    const float* __restrict__ xa, const float* __restrict__ xb, float* __restrict__ out)
{
    extern __shared__ unsigned short sm[];
    const int STG = 10240;
    int tid = threadIdx.x, lane = tid & 31, wid = tid >> 5;
    int wm = wid >> 1, wn = wid & 1;
    int bx = blockIdx.x;
    int b = bx >> 5, r5 = bx & 31;
    int p = r5 >> 3, mt = (r5 >> 1) & 3, nt = r5 & 1;
    int co0 = mt * 128, kk0 = nt * 128;
    int bp = b * 4 + p;
    int phh = (p >> 1) * 16, pww = (p & 1) * 16;
    uint32_t smb = smem_u32(sm);

    float acc[2][8][4];
#pragma unroll
    for (int i = 0; i < 2; i++)
#pragma unroll
        for (int j = 0; j < 8; j++)
#pragma unroll
            for (int q = 0; q < 4; q++) acc[i][j][q] = 0.f;

    auto issue = [&](int ch, int st) {
        int c0 = ch * 32;
        uint32_t sb = smb + (uint32_t)(st * STG) * 2;
#pragma unroll
        for (int j = 0; j < 4; j++) {
            int idx = tid + j * 256;
            int pl = idx >> 9, rem = idx & 511;
            int r = rem >> 2, c8 = (rem & 3) * 8;
            const unsigned short* src;
            if (pl == 0) src = g_wmh + (long)(co0 + r) * 128 + c0 + c8;
            else         src = g_midh + ((long)bp * 256 + kk0 + r) * 128 + c0 + c8;
            cpa16(sb + (uint32_t)(pl * 5120 + r * 40 + c8) * 2, src);
        }
    };

    issue(0, 0); CPA_COMMIT(); CPA_WAIT0();
    __syncthreads();

    for (int ch = 0; ch < 4; ch++) {
        int buf = ch & 1;
        if (ch < 3) { issue(ch + 1, buf ^ 1); CPA_COMMIT(); }
        uint32_t sstg = smb + (uint32_t)(buf * STG) * 2;
        int m0 = wm * 32;
#pragma unroll
        for (int ks = 0; ks < 32; ks += 16) {
            uint32_t ah[2][4];
#pragma unroll
            for (int mi = 0; mi < 2; mi++)
                ldsm4(ah[mi], a_addr(sstg, lane, 40, m0 + mi * 16, ks));
#pragma unroll
            for (int np = 0; np < 4; np++) {
                uint32_t bh[4];
                ldsm4(bh, b_addr(sstg + 5120 * 2, lane, 40, wn * 64 + np * 16, ks));
#pragma unroll
                for (int s = 0; s < 2; s++) {
                    int ni = np * 2 + s;
#pragma unroll
                    for (int mi = 0; mi < 2; mi++)
                        mma16816(acc[mi][ni], ah[mi][0], ah[mi][1], ah[mi][2], ah[mi][3], bh[2*s], bh[2*s+1]);
                }
            }
        }
        if (ch < 3) CPA_WAIT0();
        __syncthreads();
    }

    int g = lane >> 2, t2 = (lane & 3) * 2;
#pragma unroll
    for (int mi = 0; mi < 2; mi++)
#pragma unroll
        for (int ni = 0; ni < 8; ni++) {
            int m = co0 + wm * 32 + mi * 16 + g;
            int kk = kk0 + wn * 64 + ni * 8 + t2;
            int h = phh + (kk >> 4), w = pww + (kk & 15);
            long oa = ((long)b * C_ + m) * HW_ + h * 32 + w;
            float2 va = *(const float2*)&xa[oa];
            float2 vb = *(const float2*)&xb[oa];
            *(float2*)&out[oa] = make_float2(acc[mi][ni][0] + va.x + vb.x,
                                             acc[mi][ni][1] + va.y + vb.y);
            long ob = oa + (long)8 * HW_;
            float2 va2 = *(const float2*)&xa[ob];
            float2 vb2 = *(const float2*)&xb[ob];
            *(float2*)&out[ob] = make_float2(acc[mi][ni][2] + va2.x + vb2.x,
                                             acc[mi][ni][3] + va2.y + vb2.y);
        }
}

// ---------------------------------------------------------------------------
extern "C" void kernel_launch(void* const* d_in, const int* in_sizes, int n_in,
                              void* d_out, int out_size)
{
    const float* xa      = (const float*)d_in[0];
    const float* xb      = (const float*)d_in[1];
    const float* w_phi   = (const float*)d_in[2];
    const float* w_theta = (const float*)d_in[3];
    const float* w_g     = (const float*)d_in[4];
    const float* w_mask  = (const float*)d_in[5];
    const float* se_w1   = (const float*)d_in[6];
    const float* se_w2   = (const float*)d_in[7];
    float* out = (float*)d_out;

    const int SM_CONV = 2 * 37632 * 2;                     // 150528
    const int SM_ATT  = 2 * 11008 * 2 + 4 * 128 * 66 * 4;  // 179200
    const int SM_GEMM = 2 * 10240 * 2;                     // 40960
    cudaFuncSetAttribute(k_conv3, cudaFuncAttributeMaxDynamicSharedMemorySize, SM_CONV);
    cudaFuncSetAttribute(k_attsm, cudaFuncAttributeMaxDynamicSharedMemorySize, SM_ATT);

    k_prep_w3<<<768, 256>>>(w_phi, w_theta, w_g);   // 0
    k_prep_wm<<<256, 256>>>(w_mask);                // 1
    k_zero_part<<<1, 256>>>();                      // 2
    k_conv3<<<1024, 512, SM_CONV>>>(xa, xb);        // 3  <- profiled
    k_means<<<256, 128>>>();                        // 4
    int write_y = ((long)out_size >= OUT_ELEMS + (long)B_ * 4) ? 1 : 0;
    k_se<<<1, 64>>>(se_w1, se_w2, out + OUT_ELEMS, write_y);  // 5
    k_attsm<<<dim3(8, 64), 256, SM_ATT>>>();        // 6
    k_out5<<<dim3(2, 256), 256, SM_GEMM>>>();       // 7
    k_mask<<<2048, 256, SM_GEMM>>>(xa, xb, out);    // 8
}

// round 16
// speedup vs baseline: 1.1181x; 1.0718x over previous
#include <cuda_runtime.h>
#include <cuda_fp16.h>
#include <cstdint>
#include <math.h>

namespace {
constexpr int B_ = 64, C_ = 512, CR_ = 128, HW_ = 1024, KP_ = 256;
constexpr long OUT_ELEMS = (long)B_ * C_ * HW_;
}

// fp16 planes. hi+lo only on the softmax-feeding (A-side) operands.
__device__ __align__(256) unsigned short g_phih[B_*4*CR_*KP_];                       // B in att
__device__ __align__(256) unsigned short g_thh [B_*4*CR_*KP_], g_thl [B_*4*CR_*KP_]; // A in att
__device__ __align__(256) unsigned short g_gvh [B_*4*CR_*KP_];                       // B in out5
__device__ __align__(256) unsigned short g_atth[(long)B_*4*KP_*KP_];                 // A in out5
__device__ __align__(256) unsigned short g_midh[B_*4*KP_*CR_];                       // B in mask
__device__ __align__(256) unsigned short g_w3h[3*CR_*C_], g_w3l[3*CR_*C_];           // A in conv
__device__ __align__(256) unsigned short g_wmh[C_*CR_];                              // A in mask
__device__ __align__(256) float g_part[B_*4];
__device__ __align__(256) float g_y[B_*4];

// ------------------------------ helpers ------------------------------------
__device__ __forceinline__ uint32_t smem_u32(const void* p) {
    uint32_t a;
    asm("{ .reg .u64 t; cvta.to.shared.u64 t, %1; cvt.u32.u64 %0, t; }" : "=r"(a) : "l"(p));
    return a;
}
__device__ __forceinline__ void mma16816(float* d, uint32_t a0, uint32_t a1, uint32_t a2,
                                         uint32_t a3, uint32_t b0, uint32_t b1) {
    asm volatile(
        "mma.sync.aligned.m16n8k16.row.col.f32.f16.f16.f32 "
        "{%0,%1,%2,%3}, {%4,%5,%6,%7}, {%8,%9}, {%0,%1,%2,%3};"
        : "+f"(d[0]), "+f"(d[1]), "+f"(d[2]), "+f"(d[3])
        : "r"(a0), "r"(a1), "r"(a2), "r"(a3), "r"(b0), "r"(b1));
}
__device__ __forceinline__ void ldsm4(uint32_t* r, uint32_t a) {
    asm volatile("ldmatrix.sync.aligned.m8n8.x4.shared.b16 {%0,%1,%2,%3}, [%4];"
        : "=r"(r[0]), "=r"(r[1]), "=r"(r[2]), "=r"(r[3]) : "r"(a));
}
__device__ __forceinline__ void ldsm4t(uint32_t* r, uint32_t a) {
    asm volatile("ldmatrix.sync.aligned.m8n8.x4.trans.shared.b16 {%0,%1,%2,%3}, [%4];"
        : "=r"(r[0]), "=r"(r[1]), "=r"(r[2]), "=r"(r[3]) : "r"(a));
}
__device__ __forceinline__ uint32_t a_addr(uint32_t base, int lane, int S, int m0, int k0) {
    int mat = lane >> 3, lim = lane & 7;
    return base + (uint32_t)((m0 + lim + ((mat & 1) << 3)) * S + k0 + ((mat >> 1) << 3)) * 2;
}
__device__ __forceinline__ uint32_t b_addr(uint32_t base, int lane, int S, int n0, int k0) {
    int mat = lane >> 3, lim = lane & 7;
    return base + (uint32_t)((n0 + lim + ((mat >> 1) << 3)) * S + k0 + ((mat & 1) << 3)) * 2;
}
__device__ __forceinline__ uint32_t at_addr(uint32_t base, int lane, int S, int k0, int m0) {
    int mat = lane >> 3, lim = lane & 7;
    return base + (uint32_t)((k0 + lim + ((mat >> 1) << 3)) * S + m0 + ((mat & 1) << 3)) * 2;
}
__device__ __forceinline__ uint32_t bt_addr(uint32_t base, int lane, int S, int k0, int n0) {
    int mat = lane >> 3, lim = lane & 7;
    return base + (uint32_t)((k0 + lim + ((mat & 1) << 3)) * S + n0 + ((mat >> 1) << 3)) * 2;
}
__device__ __forceinline__ uint32_t h2(float a, float b) {
    __half2 v = __floats2half2_rn(a, b);
    return *(uint32_t*)&v;
}
__device__ __forceinline__ void hl2(float a, float b, uint32_t& h, uint32_t& l) {
    __half ha = __float2half_rn(a), hb = __float2half_rn(b);
    float ra = a - __half2float(ha), rb = b - __half2float(hb);
    __half la = __float2half_rn(ra), lb = __float2half_rn(rb);
    h = (uint32_t)*(unsigned short*)&ha | ((uint32_t)*(unsigned short*)&hb << 16);
    l = (uint32_t)*(unsigned short*)&la | ((uint32_t)*(unsigned short*)&lb << 16);
}
__device__ __forceinline__ void cpa16(uint32_t s, const void* g) {
    size_t ga;
    asm("cvta.to.global.u64 %0, %1;" : "=l"(ga) : "l"(g));
    asm volatile("cp.async.cg.shared.global [%0], [%1], 16;" :: "r"(s), "l"(ga) : "memory");
}
#define CPA_COMMIT() asm volatile("cp.async.commit_group;" ::: "memory")
#define CPA_WAIT0()  asm volatile("cp.async.wait_group 0;" ::: "memory")
__device__ __forceinline__ float hsum2(uint32_t v) {
    __half2 hv = *(__half2*)&v;
    float2 f = __half22float2(hv);
    return f.x + f.y;
}
__device__ __forceinline__ float hsum8(uint4 u) {
    return hsum2(u.x) + hsum2(u.y) + hsum2(u.z) + hsum2(u.w);
}

// ============ prep (3 launches so conv lands at profiler index 3) ==========
__global__ __launch_bounds__(256) void k_prep_w3(const float* __restrict__ wp,
    const float* __restrict__ wt, const float* __restrict__ wg)
{
    int i = blockIdx.x * 256 + threadIdx.x;      // 196608
    const float* s = (i < 65536) ? wp : (i < 131072) ? wt : wg;
    float v = s[i & 65535];
    __half h = __float2half_rn(v);
    float r = v - __half2float(h);
    __half l = __float2half_rn(r);
    g_w3h[i] = *(unsigned short*)&h; g_w3l[i] = *(unsigned short*)&l;
}
__global__ __launch_bounds__(256) void k_prep_wm(const float* __restrict__ wm)
{
    int i = blockIdx.x * 256 + threadIdx.x;      // 65536
    __half h = __float2half_rn(wm[i]);
    g_wmh[i] = *(unsigned short*)&h;
}
__global__ void k_zero_part()
{
    g_part[threadIdx.x] = 0.f;
}

// ====== K1: fused 3x 1x1 conv, double-buffered; g-conv (cv=2) is 1-pass ====
// stage: W (cv*2+pl)*5120 [128][40]; X hi-only: 30720 + t*2304 [32][72]
__global__ __launch_bounds__(256, 1) void k_conv3(
    const float* __restrict__ xa, const float* __restrict__ xb)
{
    extern __shared__ unsigned short sm[];
    const int STG = 37632;
    int tid = threadIdx.x, lane = tid & 31, wid = tid >> 5;
    int wm = wid >> 1, wn = wid & 1;
    int bx = blockIdx.x;
    int b = bx >> 4, tile = bx & 15, hwb = tile * 64;
    const float* xa_b = xa + (long)b * C_ * HW_;
    const float* xb_b = xb + (long)b * C_ * HW_;
    uint32_t smb = smem_u32(sm);

    float acc[3][2][4][4];
#pragma unroll
    for (int c = 0; c < 3; c++)
#pragma unroll
        for (int i = 0; i < 2; i++)
#pragma unroll
            for (int j = 0; j < 4; j++)
#pragma unroll
                for (int q = 0; q < 4; q++) acc[c][i][j][q] = 0.f;

    int xc = tid >> 3, xp8 = (tid & 7) * 8;
    float4 ra0, ra1, rb0, rb1;

    auto issueW = [&](int c0, int st) {
#pragma unroll
        for (int j = 0; j < 6; j++) {
            int idx = tid + j * 256;
            int wh = idx >> 9, rem = idx & 511;
            int r = rem >> 2, c8 = (rem & 3) * 8;
            long so = (long)wh * 65536 + (long)r * 512 + c0 + c8;
            uint32_t d0 = smb + (uint32_t)(st * STG + (wh * 2 + 0) * 5120 + r * 40 + c8) * 2;
            cpa16(d0, &g_w3h[so]);
            if (wh != 2) cpa16(d0 + 5120 * 2, &g_w3l[so]);   // g-conv: no lo plane
        }
    };
    auto loadX = [&](int c0) {
        long ga = (long)(c0 + xc) * HW_ + hwb + xp8;
        ra0 = *(const float4*)&xa_b[ga]; ra1 = *(const float4*)&xa_b[ga + 4];
        rb0 = *(const float4*)&xb_b[ga]; rb1 = *(const float4*)&xb_b[ga + 4];
    };
    auto storeX = [&](int st) {
        unsigned short* X = sm + st * STG + 30720;
        *(uint4*)&X[0 * 2304 + xc * 72 + xp8] = make_uint4(
            h2(ra0.x, ra0.y), h2(ra0.z, ra0.w), h2(ra1.x, ra1.y), h2(ra1.z, ra1.w));
        *(uint4*)&X[1 * 2304 + xc * 72 + xp8] = make_uint4(
            h2(rb0.x, rb0.y), h2(rb0.z, rb0.w), h2(rb1.x, rb1.y), h2(rb1.z, rb1.w));
        *(uint4*)&X[2 * 2304 + xc * 72 + xp8] = make_uint4(
            h2(ra0.x + rb0.x, ra0.y + rb0.y), h2(ra0.z + rb0.z, ra0.w + rb0.w),
            h2(ra1.x + rb1.x, ra1.y + rb1.y), h2(ra1.z + rb1.z, ra1.w + rb1.w));
    };

    issueW(0, 0); CPA_COMMIT();
    loadX(0);
    CPA_WAIT0();
    storeX(0);
    __syncthreads();

    for (int ch = 0; ch < 16; ch++) {
        int buf = ch & 1;
        if (ch < 15) {
            issueW((ch + 1) * 32, buf ^ 1); CPA_COMMIT();
            loadX((ch + 1) * 32);
        }
        uint32_t sstg = smb + (uint32_t)(buf * STG) * 2;
        int m0 = wm * 32;
#pragma unroll
        for (int ks = 0; ks < 32; ks += 16) {
#pragma unroll
            for (int cv = 0; cv < 3; cv++) {
                uint32_t Wh = sstg + (uint32_t)(cv * 2) * 5120 * 2;
                uint32_t Wl = Wh + 5120 * 2;
                uint32_t Xh = sstg + (uint32_t)(30720 + cv * 2304) * 2;
                uint32_t ah[2][4], al[2][4];
#pragma unroll
                for (int mi = 0; mi < 2; mi++) {
                    ldsm4(ah[mi], a_addr(Wh, lane, 40, m0 + mi * 16, ks));
                    if (cv != 2) ldsm4(al[mi], a_addr(Wl, lane, 40, m0 + mi * 16, ks));
                }
#pragma unroll
                for (int np = 0; np < 2; np++) {
                    uint32_t bh[4];
                    ldsm4t(bh, bt_addr(Xh, lane, 72, ks, wn * 32 + np * 16));
#pragma unroll
                    for (int s = 0; s < 2; s++) {
                        int ni = np * 2 + s;
#pragma unroll
                        for (int mi = 0; mi < 2; mi++) {
                            mma16816(acc[cv][mi][ni], ah[mi][0], ah[mi][1], ah[mi][2], ah[mi][3], bh[2*s], bh[2*s+1]);
                            if (cv != 2)
                                mma16816(acc[cv][mi][ni], al[mi][0], al[mi][1], al[mi][2], al[mi][3], bh[2*s], bh[2*s+1]);
                        }
                    }
                }
            }
        }
        if (ch < 15) {
            storeX(buf ^ 1);
            CPA_WAIT0();
        }
        __syncthreads();
    }

    int g = lane >> 2, t2 = (lane & 3) * 2;
#pragma unroll
    for (int cv = 0; cv < 3; cv++) {
#pragma unroll
        for (int mi = 0; mi < 2; mi++)
#pragma unroll
            for (int ni = 0; ni < 4; ni++) {
                int m = wm * 32 + mi * 16 + g;
                int pix = hwb + wn * 32 + ni * 8 + t2;
                int h = pix >> 5, w = pix & 31;
                int p = ((h >> 4) << 1) + (w >> 4);
                int kk = ((h & 15) << 4) + (w & 15);
                long base = ((long)((b * 4 + p) * 128 + m)) * 256 + kk;
                if (cv == 1) {      // theta: hi + lo (A-side in att)
                    uint32_t hh, ll;
                    hl2(acc[cv][mi][ni][0], acc[cv][mi][ni][1], hh, ll);
                    *(uint32_t*)&g_thh[base] = hh; *(uint32_t*)&g_thl[base] = ll;
                    hl2(acc[cv][mi][ni][2], acc[cv][mi][ni][3], hh, ll);
                    *(uint32_t*)&g_thh[base + 8 * 256] = hh; *(uint32_t*)&g_thl[base + 8 * 256] = ll;
                } else {            // phi / g: hi only (B-side)
                    unsigned short* PH = (cv == 0) ? g_phih : g_gvh;
                    *(uint32_t*)&PH[base] = h2(acc[cv][mi][ni][0], acc[cv][mi][ni][1]);
                    *(uint32_t*)&PH[base + 8 * 256] = h2(acc[cv][mi][ni][2], acc[cv][mi][ni][3]);
                }
            }
    }
}

// ============== means: y_pre[bp] = sum_c (sum_k th)(sum_l phi) ==============
__global__ __launch_bounds__(128) void k_means()
{
    __shared__ float red[128];
    int bp = blockIdx.x, c = threadIdx.x;
    long ro = ((long)bp * 128 + c) * 256;
    const uint4* th = (const uint4*)(g_thh + ro);
    const uint4* tl = (const uint4*)(g_thl + ro);
    const uint4* ph = (const uint4*)(g_phih + ro);
    float sth = 0.f, sph = 0.f;
#pragma unroll 4
    for (int j = 0; j < 32; j++) {
        sth += hsum8(th[j]) + hsum8(tl[j]);
        sph += hsum8(ph[j]);
    }
    red[c] = sth * sph;
    __syncthreads();
#pragma unroll
    for (int st = 64; st > 0; st >>= 1) {
        if (c < st) red[c] += red[c + st];
        __syncthreads();
    }
    if (c == 0) g_part[bp] = red[0];
}

// =============================== SE gate ===================================
__global__ void k_se(const float* __restrict__ se_w1, const float* __restrict__ se_w2,
                     float* __restrict__ y_out, int write_out)
{
    int b = threadIdx.x;
    if (b >= B_) return;
    float yp[4];
#pragma unroll
    for (int p = 0; p < 4; p++) yp[p] = g_part[b * 4 + p] * (1.f / 65536.f);
    float h0 = 0.f, h1 = 0.f;
#pragma unroll
    for (int p = 0; p < 4; p++) { h0 += yp[p] * se_w1[p]; h1 += yp[p] * se_w1[4 + p]; }
    h0 = fmaxf(h0, 0.f); h1 = fmaxf(h1, 0.f);
#pragma unroll
    for (int p = 0; p < 4; p++) {
        float z = h0 * se_w2[p * 2] + h1 * se_w2[p * 2 + 1];
        float yy = 1.f / (1.f + __expf(-z));
        g_y[b * 4 + p] = yy;
        if (write_out) y_out[b * 4 + p] = yy;
    }
}

// ====== K2: fused att (theta^T phi) + SE gate + patch softmax -> fp16 ======
__global__ __launch_bounds__(256, 1) void k_attsm()
{
    extern __shared__ unsigned short sm[];
    const int STG = 11008;
    float* stash = (float*)(sm + 2 * STG);  // [4][128][66]
    int tid = threadIdx.x, lane = tid & 31, wid = tid >> 5;
    int wm = wid >> 1, wn = wid & 1;
    int bxx = blockIdx.x, b = blockIdx.y;
    int kt = bxx >> 2, lt = bxx & 3;
    int k0g = kt * 128, l0g = lt * 64;
    uint32_t smb = smem_u32(sm);

    float acc[2][4][4];
#pragma unroll
    for (int i = 0; i < 2; i++)
#pragma unroll
        for (int j = 0; j < 4; j++)
#pragma unroll
            for (int q = 0; q < 4; q++) acc[i][j][q] = 0.f;

    auto issue = [&](int it, int st) {
        int p = it >> 2, c0 = (it & 3) * 32;
        long bp128 = (long)(b * 4 + p) * 128;
        uint32_t sb = smb + (uint32_t)(st * STG) * 2;
#pragma unroll
        for (int j = 0; j < 5; j++) {
            int idx = tid + j * 256;
            if (idx < 1024) {
                int pl = idx >> 9, rem = idx & 511;
                int cc = rem >> 4, k8 = (rem & 15) * 8;
                const unsigned short* src = (pl ? g_thl : g_thh) + (bp128 + c0 + cc) * 256 + k0g + k8;
                cpa16(sb + (uint32_t)(pl * 4352 + cc * 136 + k8) * 2, src);
            } else {
                int rem = idx - 1024;
                int cc = rem >> 3, l8 = (rem & 7) * 8;
                const unsigned short* src = g_phih + (bp128 + c0 + cc) * 256 + l0g + l8;
                cpa16(sb + (uint32_t)(8704 + cc * 72 + l8) * 2, src);
            }
        }
    };

    issue(0, 0); CPA_COMMIT(); CPA_WAIT0();
    __syncthreads();

    int g = lane >> 2, t2 = (lane & 3) * 2;
    for (int it = 0; it < 16; it++) {
        int buf = it & 1;
        if (it < 15) { issue(it + 1, buf ^ 1); CPA_COMMIT(); }
        uint32_t sstg = smb + (uint32_t)(buf * STG) * 2;
        int m0 = wm * 32;
#pragma unroll
        for (int ks = 0; ks < 32; ks += 16) {
            uint32_t ah[2][4], al[2][4];
#pragma unroll
            for (int mi = 0; mi < 2; mi++) {
                ldsm4t(ah[mi], at_addr(sstg,            lane, 136, ks, m0 + mi * 16));
                ldsm4t(al[mi], at_addr(sstg + 4352 * 2, lane, 136, ks, m0 + mi * 16));
            }
#pragma unroll
            for (int np = 0; np < 2; np++) {
                uint32_t bh[4];
                ldsm4t(bh, bt_addr(sstg + 8704 * 2, lane, 72, ks, wn * 32 + np * 16));
#pragma unroll
                for (int s = 0; s < 2; s++) {
                    int ni = np * 2 + s;
#pragma unroll
                    for (int mi = 0; mi < 2; mi++) {
                        mma16816(acc[mi][ni], ah[mi][0], ah[mi][1], ah[mi][2], ah[mi][3], bh[2*s], bh[2*s+1]);
                        mma16816(acc[mi][ni], al[mi][0], al[mi][1], al[mi][2], al[mi][3], bh[2*s], bh[2*s+1]);
                    }
                }
            }
        }
        if ((it & 3) == 3) {
            int p = it >> 2;
            float* sp = stash + p * 128 * 66;
#pragma unroll
            for (int mi = 0; mi < 2; mi++)
#pragma unroll
                for (int ni = 0; ni < 4; ni++) {
                    int m = wm * 32 + mi * 16 + g;
                    int l = wn * 32 + ni * 8 + t2;
                    sp[m * 66 + l]     = acc[mi][ni][0];
                    sp[m * 66 + l + 1] = acc[mi][ni][1];
                    sp[(m + 8) * 66 + l]     = acc[mi][ni][2];
                    sp[(m + 8) * 66 + l + 1] = acc[mi][ni][3];
                    acc[mi][ni][0] = acc[mi][ni][1] = acc[mi][ni][2] = acc[mi][ni][3] = 0.f;
                }
        }
        if (it < 15) CPA_WAIT0();
        __syncthreads();
    }

    float yv[4];
#pragma unroll
    for (int p = 0; p < 4; p++) yv[p] = g_y[b * 4 + p];
#pragma unroll
    for (int mi = 0; mi < 2; mi++)
#pragma unroll
        for (int ni = 0; ni < 4; ni++) {
            int m = wm * 32 + mi * 16 + g;
            int l = wn * 32 + ni * 8 + t2;
#pragma unroll
            for (int rr = 0; rr < 2; rr++) {
                int mm = m + rr * 8;
                float v0[4], v1[4];
#pragma unroll
                for (int p = 0; p < 4; p++) {
                    v0[p] = stash[p * 128 * 66 + mm * 66 + l] * yv[p];
                    v1[p] = stash[p * 128 * 66 + mm * 66 + l + 1] * yv[p];
                }
                float mx0 = fmaxf(fmaxf(v0[0], v0[1]), fmaxf(v0[2], v0[3]));
                float mx1 = fmaxf(fmaxf(v1[0], v1[1]), fmaxf(v1[2], v1[3]));
                float e0[4], e1[4], s0 = 0.f, s1 = 0.f;
#pragma unroll
                for (int p = 0; p < 4; p++) {
                    e0[p] = __expf(v0[p] - mx0); s0 += e0[p];
                    e1[p] = __expf(v1[p] - mx1); s1 += e1[p];
                }
                float i0 = 1.f / s0, i1 = 1.f / s1;
#pragma unroll
                for (int p = 0; p < 4; p++) {
                    long off = ((long)(b * 4 + p) * 256 + k0g + mm) * 256 + l0g + l;
                    *(uint32_t*)&g_atth[off] = h2(e0[p] * i0, e1[p] * i1);
                }
            }
        }
}

// ======== K5: mid[k][cr] = att @ g^T (1-pass) ==============================
__global__ __launch_bounds__(256) void k_out5()
{
    extern __shared__ unsigned short sm[];
    const int STG = 10240;
    int tid = threadIdx.x, lane = tid & 31, wid = tid >> 5;
    int wm = wid >> 1, wn = wid & 1;
    int bp = blockIdx.y;
    int k0 = blockIdx.x * 128;
    uint32_t smb = smem_u32(sm);

    float acc[2][8][4];
#pragma unroll
    for (int i = 0; i < 2; i++)
#pragma unroll
        for (int j = 0; j < 8; j++)
#pragma unroll
            for (int q = 0; q < 4; q++) acc[i][j][q] = 0.f;

    auto issue = [&](int ch, int st) {
        int l0 = ch * 32;
        uint32_t sb = smb + (uint32_t)(st * STG) * 2;
#pragma unroll
        for (int j = 0; j < 4; j++) {
            int idx = tid + j * 256;
            int pl = idx >> 9, rem = idx & 511;
            int r = rem >> 2, c8 = (rem & 3) * 8;
            const unsigned short* src;
            if (pl == 0) src = g_atth + ((long)bp * 256 + k0 + r) * 256 + l0 + c8;
            else         src = g_gvh  + ((long)bp * 128 + r) * 256 + l0 + c8;
            cpa16(sb + (uint32_t)(pl * 5120 + r * 40 + c8) * 2, src);
        }
    };

    issue(0, 0); CPA_COMMIT(); CPA_WAIT0();
    __syncthreads();

    for (int ch = 0; ch < 8; ch++) {
        int buf = ch & 1;
        if (ch < 7) { issue(ch + 1, buf ^ 1); CPA_COMMIT(); }
        uint32_t sstg = smb + (uint32_t)(buf * STG) * 2;
        int m0 = wm * 32;
#pragma unroll
        for (int ks = 0; ks < 32; ks += 16) {
            uint32_t ah[2][4];
#pragma unroll
            for (int mi = 0; mi < 2; mi++)
                ldsm4(ah[mi], a_addr(sstg, lane, 40, m0 + mi * 16, ks));
#pragma unroll
            for (int np = 0; np < 4; np++) {
                uint32_t bh[4];
                ldsm4(bh, b_addr(sstg + 5120 * 2, lane, 40, wn * 64 + np * 16, ks));
#pragma unroll
                for (int s = 0; s < 2; s++) {
                    int ni = np * 2 + s;
#pragma unroll
                    for (int mi = 0; mi < 2; mi++)
                        mma16816(acc[mi][ni], ah[mi][0], ah[mi][1], ah[mi][2], ah[mi][3], bh[2*s], bh[2*s+1]);
                }
            }
        }
        if (ch < 7) CPA_WAIT0();
        __syncthreads();
    }

    int g = lane >> 2, t2 = (lane & 3) * 2;
#pragma unroll
    for (int mi = 0; mi < 2; mi++)
#pragma unroll
        for (int ni = 0; ni < 8; ni++) {
            int m = k0 + wm * 32 + mi * 16 + g;
            int n = wn * 64 + ni * 8 + t2;
            long off = ((long)bp * 256 + m) * 128 + n;
            *(uint32_t*)&g_midh[off] = h2(acc[mi][ni][0], acc[mi][ni][1]);
            *(uint32_t*)&g_midh[off + 8 * 128] = h2(acc[mi][ni][2], acc[mi][ni][3]);
        }
}

// ======= K6: mask conv + residual (1-pass) =================================
__global__ __launch_bounds__(256) void k_mask(
    const float* __restrict__ xa, const float* __restrict__ xb, float* __restrict__ out)
{
    extern __shared__ unsigned short sm[];
    const int STG = 10240;
    int tid = threadIdx.x, lane = tid & 31, wid = tid >> 5;
    int wm = wid >> 1, wn = wid & 1;
    int bx = blockIdx.x;
    int b = bx >> 5, r5 = bx & 31;
    int p = r5 >> 3, mt = (r5 >> 1) & 3, nt = r5 & 1;
    int co0 = mt * 128, kk0 = nt * 128;
    int bp = b * 4 + p;
    int phh = (p >> 1) * 16, pww = (p & 1) * 16;
    uint32_t smb = smem_u32(sm);

    float acc[2][8][4];
#pragma unroll
    for (int i = 0; i < 2; i++)
#pragma unroll
        for (int j = 0; j < 8; j++)
#pragma unroll
            for (int q = 0; q < 4; q++) acc[i][j][q] = 0.f;

    auto issue = [&](int ch, int st) {
        int c0 = ch * 32;
        uint32_t sb = smb + (uint32_t)(st * STG) * 2;
#pragma unroll
        for (int j = 0; j < 4; j++) {
            int idx = tid + j * 256;
            int pl = idx >> 9, rem = idx & 511;
            int r = rem >> 2, c8 = (rem & 3) * 8;
            const unsigned short* src;
            if (pl == 0) src = g_wmh + (long)(co0 + r) * 128 + c0 + c8;
            else         src = g_midh + ((long)bp * 256 + kk0 + r) * 128 + c0 + c8;
            cpa16(sb + (uint32_t)(pl * 5120 + r * 40 + c8) * 2, src);
        }
    };

    issue(0, 0); CPA_COMMIT(); CPA_WAIT0();
    __syncthreads();

    for (int ch = 0; ch < 4; ch++) {
        int buf = ch & 1;
        if (ch < 3) { issue(ch + 1, buf ^ 1); CPA_COMMIT(); }
        uint32_t sstg = smb + (uint32_t)(buf * STG) * 2;
        int m0 = wm * 32;
#pragma unroll
        for (int ks = 0; ks < 32; ks += 16) {
            uint32_t ah[2][4];
#pragma unroll
            for (int mi = 0; mi < 2; mi++)
                ldsm4(ah[mi], a_addr(sstg, lane, 40, m0 + mi * 16, ks));
#pragma unroll
            for (int np = 0; np < 4; np++) {
                uint32_t bh[4];
                ldsm4(bh, b_addr(sstg + 5120 * 2, lane, 40, wn * 64 + np * 16, ks));
#pragma unroll
                for (int s = 0; s < 2; s++) {
                    int ni = np * 2 + s;
#pragma unroll
                    for (int mi = 0; mi < 2; mi++)
                        mma16816(acc[mi][ni], ah[mi][0], ah[mi][1], ah[mi][2], ah[mi][3], bh[2*s], bh[2*s+1]);
                }
            }
        }
        if (ch < 3) CPA_WAIT0();
        __syncthreads();
    }

    int g = lane >> 2, t2 = (lane & 3) * 2;
#pragma unroll
    for (int mi = 0; mi < 2; mi++)
#pragma unroll
        for (int ni = 0; ni < 8; ni++) {
            int m = co0 + wm * 32 + mi * 16 + g;
            int kk = kk0 + wn * 64 + ni * 8 + t2;
            int h = phh + (kk >> 4), w = pww + (kk & 15);
            long oa = ((long)b * C_ + m) * HW_ + h * 32 + w;
            float2 va = *(const float2*)&xa[oa];
            float2 vb = *(const float2*)&xb[oa];
            *(float2*)&out[oa] = make_float2(acc[mi][ni][0] + va.x + vb.x,
                                             acc[mi][ni][1] + va.y + vb.y);
            long ob = oa + (long)8 * HW_;
            float2 va2 = *(const float2*)&xa[ob];
            float2 vb2 = *(const float2*)&xb[ob];
            *(float2*)&out[ob] = make_float2(acc[mi][ni][2] + va2.x + vb2.x,
                                             acc[mi][ni][3] + va2.y + vb2.y);
        }
}

// ---------------------------------------------------------------------------
extern "C" void kernel_launch(void* const* d_in, const int* in_sizes, int n_in,
                              void* d_out, int out_size)
{
    const float* xa      = (const float*)d_in[0];
    const float* xb      = (const float*)d_in[1];
    const float* w_phi   = (const float*)d_in[2];
    const float* w_theta = (const float*)d_in[3];
    const float* w_g     = (const float*)d_in[4];
    const float* w_mask  = (const float*)d_in[5];
    const float* se_w1   = (const float*)d_in[6];
    const float* se_w2   = (const float*)d_in[7];
    float* out = (float*)d_out;

    const int SM_CONV = 2 * 37632 * 2;                     // 150528
    const int SM_ATT  = 2 * 11008 * 2 + 4 * 128 * 66 * 4;  // 179200
    const int SM_GEMM = 2 * 10240 * 2;                     // 40960
    cudaFuncSetAttribute(k_conv3, cudaFuncAttributeMaxDynamicSharedMemorySize, SM_CONV);
    cudaFuncSetAttribute(k_attsm, cudaFuncAttributeMaxDynamicSharedMemorySize, SM_ATT);

    k_prep_w3<<<768, 256>>>(w_phi, w_theta, w_g);   // 0
    k_prep_wm<<<256, 256>>>(w_mask);                // 1
    k_zero_part<<<1, 256>>>();                      // 2
    k_conv3<<<1024, 256, SM_CONV>>>(xa, xb);        // 3  <- profiled
    k_means<<<256, 128>>>();                        // 4
    int write_y = ((long)out_size >= OUT_ELEMS + (long)B_ * 4) ? 1 : 0;
    k_se<<<1, 64>>>(se_w1, se_w2, out + OUT_ELEMS, write_y);  // 5
    k_attsm<<<dim3(8, 64), 256, SM_ATT>>>();        // 6
    k_out5<<<dim3(2, 256), 256, SM_GEMM>>>();       // 7
    k_mask<<<2048, 256, SM_GEMM>>>(xa, xb, out);    // 8
}